// round 1
// baseline (speedup 1.0000x reference)
#include <cuda_runtime.h>

// Permutation: out[b,i,j,W,p,q] = x[b, 2i+p, 2j+q, W]
// x: (16, 64, 224, 224) fp32, out same element count.
// One block per (b,i,j) segment (57344 blocks), 224 threads = one W each.
// Each thread gathers 4 floats (4 coalesced-by-warp LDG.32) and writes one
// contiguous float4 (coalesced STG.128).

#define H 224
#define W_DIM 224
#define C 64
#define JN 112   // h/2
#define IN 32    // c/2

__global__ void __launch_bounds__(224) KernelActivation_perm(
    const float* __restrict__ x, float4* __restrict__ out)
{
    const int w   = threadIdx.x;        // 0..223
    const int seg = blockIdx.x;         // 0..57343 = b*IN*JN + i*JN + j
    const int j   = seg % JN;
    const int t   = seg / JN;
    const int i   = t & (IN - 1);       // t % 32
    const int b   = t >> 5;             // t / 32

    // base = index of x[b, 2i, 2j, w]
    const int base = ((b * C + 2 * i) * H + 2 * j) * W_DIM + w;

    float4 v;
    v.x = x[base];                       // p=0,q=0
    v.y = x[base + W_DIM];               // p=0,q=1
    v.z = x[base + H * W_DIM];           // p=1,q=0
    v.w = x[base + H * W_DIM + W_DIM];   // p=1,q=1

    out[seg * W_DIM + w] = v;
}

extern "C" void kernel_launch(void* const* d_in, const int* in_sizes, int n_in,
                              void* d_out, int out_size)
{
    const float* x = (const float*)d_in[0];
    float4* out = (float4*)d_out;
    // segments = b * (c/2) * (h/2) = 16 * 32 * 112 = 57344
    KernelActivation_perm<<<57344, 224>>>(x, out);
}

// round 2
// speedup vs baseline: 1.0377x; 1.0377x over previous
#include <cuda_runtime.h>

// Permutation: out[b,i,j,W,p,q] = x[b, 2i+p, 2j+q, W]   (k=2 unfold repack)
// x: (16, 64, 224, 224) fp32. Pure streaming permutation, HBM-bound.
//
// Strategy: one block = 4 consecutive segments (seg = b*32*112 + i*112 + j).
//  - Load phase : each thread owns (segment sl, W-group wg) and reads one
//                 float4 (4 consecutive W) from each of the 4 source rows
//                 -> 4x LDG.128, 512B contiguous per warp per instruction.
//  - Interleave : transpose the 4x4 in registers, stage to shared memory.
//  - Store phase: drain smem with fully contiguous STG.128 (512B/warp).
// Global wavefronts stay optimal on both sides; load instruction count is
// 4x lower than the scalar-gather version. Streaming cache hints (.cs)
// since every byte is touched exactly once.

#define H 224
#define W_DIM 224
#define C 64
#define JN 112          // h/2
#define IN 32           // c/2
#define W4 56           // W_DIM / 4 float4 groups per row
#define SEGS_PER_BLOCK 4
#define THREADS 224     // SEGS_PER_BLOCK * W4

__global__ void __launch_bounds__(THREADS) KernelActivation_perm2(
    const float4* __restrict__ x4, float4* __restrict__ out4)
{
    __shared__ float4 s[SEGS_PER_BLOCK * W_DIM];   // 14336 B

    const int tid  = threadIdx.x;
    const int sl   = tid / W4;          // 0..3 local segment
    const int wg   = tid % W4;          // 0..55 W-group (4 floats)
    const int seg4 = blockIdx.x * SEGS_PER_BLOCK;
    const int seg  = seg4 + sl;

    const int j = seg % JN;
    const int t = seg / JN;
    const int i = t & (IN - 1);
    const int b = t >> 5;

    // source row index (rows of 224 floats = 56 float4): x[b, 2i+p, 2j+q, :]
    const int row00 = ((b * C + 2 * i) * H + 2 * j);
    const long base = (long)row00 * W4 + wg;

    const float4 r00 = __ldcs(&x4[base]);                 // p=0 q=0
    const float4 r01 = __ldcs(&x4[base + W4]);            // p=0 q=1
    const float4 r10 = __ldcs(&x4[base + (long)H * W4]);  // p=1 q=0
    const float4 r11 = __ldcs(&x4[base + (long)H * W4 + W4]); // p=1 q=1

    // 4x4 register transpose: out4[w] = {r00[w], r01[w], r10[w], r11[w]}
    float4* sp = &s[sl * W_DIM + 4 * wg];
    sp[0] = make_float4(r00.x, r01.x, r10.x, r11.x);
    sp[1] = make_float4(r00.y, r01.y, r10.y, r11.y);
    sp[2] = make_float4(r00.z, r01.z, r10.z, r11.z);
    sp[3] = make_float4(r00.w, r01.w, r10.w, r11.w);

    __syncthreads();

    // contiguous drain: block writes 4*224 float4 = 14336B back-to-back
    float4* dst = &out4[(long)seg4 * W_DIM];
#pragma unroll
    for (int m = 0; m < 4; m++) {
        const int idx = m * THREADS + tid;
        __stcs(&dst[idx], s[idx]);
    }
}

extern "C" void kernel_launch(void* const* d_in, const int* in_sizes, int n_in,
                              void* d_out, int out_size)
{
    const float4* x4 = (const float4*)d_in[0];
    float4* out4 = (float4*)d_out;
    // 57344 segments / 4 per block
    KernelActivation_perm2<<<14336, THREADS>>>(x4, out4);
}